// round 2
// baseline (speedup 1.0000x reference)
#include <cuda_runtime.h>

// ---------------- problem constants ----------------
#define CC      64
#define HH      120
#define WW      120
#define NBOX    8192
#define HID     128
#define SCOORD  (119.0f / 960.0f)

#define FIN_A   576
#define FIN_B   3136
#define FIN_C   7744
#define FIN_TOT (FIN_A + FIN_B + FIN_C)

// ---------------- device scratch ----------------
__device__ float d_fmT[HH * WW * CC];          // [y][x][c]
__device__ float d_W1T[FIN_TOT * HID];         // pos-major permuted W1^T
__device__ float d_gf[CC];
__device__ float d_g[16];

// ---------------- f32x2 helpers ----------------
__device__ __forceinline__ unsigned long long pack2(float x) {
    unsigned long long r;
    asm("mov.b64 %0, {%1, %1};" : "=l"(r) : "r"(__float_as_uint(x)));
    return r;
}
__device__ __forceinline__ void fma2(unsigned long long& d,
                                     unsigned long long a,
                                     unsigned long long b) {
    asm("fma.rn.f32x2 %0, %1, %2, %0;" : "+l"(d) : "l"(a), "l"(b));
}

// ---------------- prep kernels ----------------
__global__ void transpose_fm_kernel(const float* __restrict__ fm) {
    int idx = blockIdx.x * 256 + threadIdx.x;
    int c = idx & 63;
    int p = idx >> 6;
    d_fmT[idx] = fm[c * (HH * WW) + p];
}

__global__ void transpose_w1_kernel(const float* __restrict__ W1, int fin, int r2, int base) {
    int idx = blockIdx.x * 256 + threadIdx.x;
    if (idx >= fin * HID) return;
    int n   = idx & 127;
    int kp  = idx >> 7;
    int c   = kp & 63;
    int pos = kp >> 6;
    d_W1T[base + idx] = W1[n * fin + c * r2 + pos];
}

__global__ void gf_kernel(const float* __restrict__ fm) {
    int c = blockIdx.x;
    float s = 0.0f;
    for (int i = threadIdx.x; i < HH * WW; i += 256) s += fm[c * (HH * WW) + i];
    __shared__ float red[8];
    #pragma unroll
    for (int off = 16; off; off >>= 1) s += __shfl_down_sync(0xffffffffu, s, off);
    if ((threadIdx.x & 31) == 0) red[threadIdx.x >> 5] = s;
    __syncthreads();
    if (threadIdx.x < 8) {
        s = red[threadIdx.x];
        #pragma unroll
        for (int off = 4; off; off >>= 1) s += __shfl_down_sync(0xffu, s, off);
        if (threadIdx.x == 0) d_gf[c] = s / (float)(HH * WW);
    }
}

__global__ void g_kernel(const float* __restrict__ Wg, const float* __restrict__ bg) {
    int j = threadIdx.x;
    float s = bg[j];
    #pragma unroll 8
    for (int c = 0; c < CC; c++) s += d_gf[c] * Wg[j * CC + c];
    d_g[j] = s;
}

__global__ void g_write_kernel(float* __restrict__ out) {
    int idx = blockIdx.x * 256 + threadIdx.x;
    int m = idx >> 4;
    int j = idx & 15;
    out[m * 64 + 48 + j] = d_g[j];
}

// ---------------- unified fused head kernel ----------------
// 128 threads per CTA. Tile: 64 boxes x 128 hidden, thread tile 8m x 8n.
// K-tile = 16 (one quarter-position of 64 channels). Double-buffered smem.

struct Pref {
    float4 t00a, t00b, t01a, t01b, t10a, t10b, t11a, t11b;  // 4 taps x 2 float4 (8 ch)
    float  w00, w01, w10, w11;
    float4 b0, b1, b2, b3;                                  // W1T slab
};

__device__ __forceinline__ Pref do_prefetch(int kt, int r, float invr,
                                            const float* __restrict__ boxp,
                                            const float* __restrict__ w1t,
                                            int m, int half, int tid) {
    Pref p;
    int pos = kt >> 2;
    int q   = kt & 3;
    int py  = pos / r;
    int px  = pos - py * r;
    float tx = px * invr;
    float ty = py * invr;

    const float4 bp = *reinterpret_cast<const float4*>(&boxp[m * 4]);
    float ix = fmaf(bp.y, tx, bp.x);
    float iy = fmaf(bp.w, ty, bp.z);
    float x0f = floorf(ix), y0f = floorf(iy);
    float wx = ix - x0f, wy = iy - y0f;
    int x0 = (int)x0f, y0 = (int)y0f;
    int x1 = x0 + 1,   y1 = y0 + 1;
    float vx0 = (x0 >= 0 && x0 < WW) ? 1.0f : 0.0f;
    float vx1 = (x1 >= 0 && x1 < WW) ? 1.0f : 0.0f;
    float vy0 = (y0 >= 0 && y0 < HH) ? 1.0f : 0.0f;
    float vy1 = (y1 >= 0 && y1 < HH) ? 1.0f : 0.0f;
    p.w00 = (1.0f - wx) * (1.0f - wy) * vx0 * vy0;
    p.w01 = wx * (1.0f - wy) * vx1 * vy0;
    p.w10 = (1.0f - wx) * wy * vx0 * vy1;
    p.w11 = wx * wy * vx1 * vy1;
    int cx0 = min(max(x0, 0), WW - 1), cx1 = min(max(x1, 0), WW - 1);
    int cy0 = min(max(y0, 0), HH - 1), cy1 = min(max(y1, 0), HH - 1);

    const float4* f = reinterpret_cast<const float4*>(d_fmT);
    int cq  = q * 4 + half * 2;
    int o00 = (cy0 * WW + cx0) * 16 + cq;
    int o01 = (cy0 * WW + cx1) * 16 + cq;
    int o10 = (cy1 * WW + cx0) * 16 + cq;
    int o11 = (cy1 * WW + cx1) * 16 + cq;
    p.t00a = __ldg(&f[o00]); p.t00b = __ldg(&f[o00 + 1]);
    p.t01a = __ldg(&f[o01]); p.t01b = __ldg(&f[o01 + 1]);
    p.t10a = __ldg(&f[o10]); p.t10b = __ldg(&f[o10 + 1]);
    p.t11a = __ldg(&f[o11]); p.t11b = __ldg(&f[o11 + 1]);

    const float4* wb = reinterpret_cast<const float4*>(w1t + (size_t)kt * 2048);
    p.b0 = __ldg(&wb[tid]);
    p.b1 = __ldg(&wb[tid + 128]);
    p.b2 = __ldg(&wb[tid + 256]);
    p.b3 = __ldg(&wb[tid + 384]);
    return p;
}

__global__ void __launch_bounds__(128)
unified_head_kernel(const float* __restrict__ boxes,
                    const float* __restrict__ b1a, const float* __restrict__ W2a,
                    const float* __restrict__ b2a,
                    const float* __restrict__ b1b, const float* __restrict__ W2b,
                    const float* __restrict__ b2b,
                    const float* __restrict__ b1c, const float* __restrict__ W2c,
                    const float* __restrict__ b2c,
                    const float* __restrict__ scale_w,
                    float* __restrict__ out) {
    __shared__ float pool[8192];   // dbuf: 2 x (As 1024 | Bs 2048); phase2: Hs 64x128
    __shared__ float boxp[256];

    const int tid = threadIdx.x;
    const int bid = blockIdx.x;

    // head selection: c first (longest blocks launch earliest)
    const float *b1, *W2, *b2;
    int fin, r, od, col0, swi, w1tbase;
    float invr;
    if (bid < 128) {
        b1 = b1c; W2 = W2c; b2 = b2c;
        fin = FIN_C; r = 11; invr = 0.1f; od = 5;  col0 = 43; swi = 2;
        w1tbase = (FIN_A + FIN_B) * HID;
    } else if (bid < 256) {
        b1 = b1b; W2 = W2b; b2 = b2b;
        fin = FIN_B; r = 7;  invr = 1.0f / 6.0f; od = 21; col0 = 22; swi = 1;
        w1tbase = FIN_A * HID;
    } else {
        b1 = b1a; W2 = W2a; b2 = b2a;
        fin = FIN_A; r = 3;  invr = 0.5f; od = 22; col0 = 0;  swi = 0;
        w1tbase = 0;
    }
    const int box0 = (bid & 127) * 64;

    if (tid < 64) {
        float4 b4 = __ldg(reinterpret_cast<const float4*>(boxes) + (box0 + tid));
        float4 o;
        o.x = b4.x * SCOORD;
        o.y = (b4.z - b4.x) * SCOORD;
        o.z = b4.y * SCOORD;
        o.w = (b4.w - b4.y) * SCOORD;
        *reinterpret_cast<float4*>(&boxp[tid * 4]) = o;
    }
    __syncthreads();

    const float* w1t = d_W1T + w1tbase;
    const int ntiles = fin >> 4;

    // roles
    const int m    = tid & 63;        // im2col: box
    const int half = tid >> 6;        // im2col: channel half (0/1)
    const int m0   = (tid >> 4) << 3; // gemm: 8 boxes
    const int n0   = (tid & 15) << 3; // gemm: 8 hidden

    unsigned long long acc[4][8];     // [m-pair][n]
    #pragma unroll
    for (int i = 0; i < 4; i++)
        #pragma unroll
        for (int j = 0; j < 8; j++) acc[i][j] = 0ull;

    Pref p = do_prefetch(0, r, invr, boxp, w1t, m, half, tid);

    for (int kt = 0; kt < ntiles; ++kt) {
        float* As = pool + (kt & 1) * 3072;
        float* Bs = As + 1024;

        // combine taps -> A tile [kl][64]
        {
            float4 v;
            int kl = half * 8;
            v.x = p.w00 * p.t00a.x + p.w01 * p.t01a.x + p.w10 * p.t10a.x + p.w11 * p.t11a.x;
            v.y = p.w00 * p.t00a.y + p.w01 * p.t01a.y + p.w10 * p.t10a.y + p.w11 * p.t11a.y;
            v.z = p.w00 * p.t00a.z + p.w01 * p.t01a.z + p.w10 * p.t10a.z + p.w11 * p.t11a.z;
            v.w = p.w00 * p.t00a.w + p.w01 * p.t01a.w + p.w10 * p.t10a.w + p.w11 * p.t11a.w;
            As[(kl + 0) * 64 + m] = v.x;
            As[(kl + 1) * 64 + m] = v.y;
            As[(kl + 2) * 64 + m] = v.z;
            As[(kl + 3) * 64 + m] = v.w;
            v.x = p.w00 * p.t00b.x + p.w01 * p.t01b.x + p.w10 * p.t10b.x + p.w11 * p.t11b.x;
            v.y = p.w00 * p.t00b.y + p.w01 * p.t01b.y + p.w10 * p.t10b.y + p.w11 * p.t11b.y;
            v.z = p.w00 * p.t00b.z + p.w01 * p.t01b.z + p.w10 * p.t10b.z + p.w11 * p.t11b.z;
            v.w = p.w00 * p.t00b.w + p.w01 * p.t01b.w + p.w10 * p.t10b.w + p.w11 * p.t11b.w;
            As[(kl + 4) * 64 + m] = v.x;
            As[(kl + 5) * 64 + m] = v.y;
            As[(kl + 6) * 64 + m] = v.z;
            As[(kl + 7) * 64 + m] = v.w;
        }
        *reinterpret_cast<float4*>(&Bs[tid * 4])        = p.b0;
        *reinterpret_cast<float4*>(&Bs[512 + tid * 4])  = p.b1;
        *reinterpret_cast<float4*>(&Bs[1024 + tid * 4]) = p.b2;
        *reinterpret_cast<float4*>(&Bs[1536 + tid * 4]) = p.b3;
        __syncthreads();

        int ktn = (kt + 1 < ntiles) ? kt + 1 : kt;
        Pref pn = do_prefetch(ktn, r, invr, boxp, w1t, m, half, tid);

        #pragma unroll
        for (int k = 0; k < 16; k++) {
            ulonglong2 a01 = *reinterpret_cast<const ulonglong2*>(&As[k * 64 + m0]);
            ulonglong2 a23 = *reinterpret_cast<const ulonglong2*>(&As[k * 64 + m0 + 4]);
            float4 bA = *reinterpret_cast<const float4*>(&Bs[k * 128 + n0]);
            float4 bB = *reinterpret_cast<const float4*>(&Bs[k * 128 + n0 + 4]);
            unsigned long long bp;
            bp = pack2(bA.x);
            fma2(acc[0][0], a01.x, bp); fma2(acc[1][0], a01.y, bp);
            fma2(acc[2][0], a23.x, bp); fma2(acc[3][0], a23.y, bp);
            bp = pack2(bA.y);
            fma2(acc[0][1], a01.x, bp); fma2(acc[1][1], a01.y, bp);
            fma2(acc[2][1], a23.x, bp); fma2(acc[3][1], a23.y, bp);
            bp = pack2(bA.z);
            fma2(acc[0][2], a01.x, bp); fma2(acc[1][2], a01.y, bp);
            fma2(acc[2][2], a23.x, bp); fma2(acc[3][2], a23.y, bp);
            bp = pack2(bA.w);
            fma2(acc[0][3], a01.x, bp); fma2(acc[1][3], a01.y, bp);
            fma2(acc[2][3], a23.x, bp); fma2(acc[3][3], a23.y, bp);
            bp = pack2(bB.x);
            fma2(acc[0][4], a01.x, bp); fma2(acc[1][4], a01.y, bp);
            fma2(acc[2][4], a23.x, bp); fma2(acc[3][4], a23.y, bp);
            bp = pack2(bB.y);
            fma2(acc[0][5], a01.x, bp); fma2(acc[1][5], a01.y, bp);
            fma2(acc[2][5], a23.x, bp); fma2(acc[3][5], a23.y, bp);
            bp = pack2(bB.z);
            fma2(acc[0][6], a01.x, bp); fma2(acc[1][6], a01.y, bp);
            fma2(acc[2][6], a23.x, bp); fma2(acc[3][6], a23.y, bp);
            bp = pack2(bB.w);
            fma2(acc[0][7], a01.x, bp); fma2(acc[1][7], a01.y, bp);
            fma2(acc[2][7], a23.x, bp); fma2(acc[3][7], a23.y, bp);
        }
        p = pn;
    }
    __syncthreads();   // all reads of dbuf done before Hs overwrite

    // layer-1 bias + relu -> Hs[64][128]
    float* Hs = pool;
    float b1v[8];
    #pragma unroll
    for (int j = 0; j < 8; j++) b1v[j] = __ldg(&b1[n0 + j]);
    #pragma unroll
    for (int i = 0; i < 4; i++) {
        #pragma unroll
        for (int j = 0; j < 8; j++) {
            unsigned long long v = acc[i][j];
            float f0 = __uint_as_float((unsigned int)v)         + b1v[j];
            float f1 = __uint_as_float((unsigned int)(v >> 32)) + b1v[j];
            Hs[(m0 + 2 * i)     * 128 + n0 + j] = fmaxf(f0, 0.0f);
            Hs[(m0 + 2 * i + 1) * 128 + n0 + j] = fmaxf(f1, 0.0f);
        }
    }
    __syncthreads();

    // layer-2
    const float sw = __ldg(&scale_w[swi]);
    const int njobs = od << 6;
    for (int job = tid; job < njobs; job += 128) {
        int mm = job / od;
        int o  = job - mm * od;
        float s = __ldg(&b2[o]);
        const float4* hrow = reinterpret_cast<const float4*>(&Hs[mm * 128]);
        const float4* wrow = reinterpret_cast<const float4*>(&W2[o * 128]);
        #pragma unroll 8
        for (int qq = 0; qq < 32; qq++) {
            float4 h4 = hrow[qq];
            float4 w4 = __ldg(&wrow[qq]);
            s += h4.x * w4.x + h4.y * w4.y + h4.z * w4.z + h4.w * w4.w;
        }
        out[(size_t)(box0 + mm) * 64 + col0 + o] = fmaxf(s, 0.0f) * sw;
    }
}

// ---------------- launch ----------------
extern "C" void kernel_launch(void* const* d_in, const int* in_sizes, int n_in,
                              void* d_out, int out_size) {
    const float* fm      = (const float*)d_in[0];
    const float* boxes   = (const float*)d_in[1];
    const float* W1a     = (const float*)d_in[2];
    const float* b1a     = (const float*)d_in[3];
    const float* W2a     = (const float*)d_in[4];
    const float* b2a     = (const float*)d_in[5];
    const float* W1b     = (const float*)d_in[6];
    const float* b1b     = (const float*)d_in[7];
    const float* W2b     = (const float*)d_in[8];
    const float* b2b     = (const float*)d_in[9];
    const float* W1c     = (const float*)d_in[10];
    const float* b1c     = (const float*)d_in[11];
    const float* W2c     = (const float*)d_in[12];
    const float* b2c     = (const float*)d_in[13];
    const float* scale_w = (const float*)d_in[14];
    const float* Wg      = (const float*)d_in[15];
    const float* bg      = (const float*)d_in[16];
    float* out = (float*)d_out;

    transpose_fm_kernel<<<(HH * WW * CC) / 256, 256>>>(fm);
    transpose_w1_kernel<<<(FIN_A * HID) / 256, 256>>>(W1a, FIN_A, 9, 0);
    transpose_w1_kernel<<<(FIN_B * HID) / 256, 256>>>(W1b, FIN_B, 49, FIN_A * HID);
    transpose_w1_kernel<<<(FIN_C * HID + 255) / 256, 256>>>(W1c, FIN_C, 121, (FIN_A + FIN_B) * HID);
    gf_kernel<<<CC, 256>>>(fm);
    g_kernel<<<1, 16>>>(Wg, bg);
    g_write_kernel<<<(NBOX * 16) / 256, 256>>>(out);

    unified_head_kernel<<<384, 128>>>(boxes,
                                      b1a, W2a, b2a,
                                      b1b, W2b, b2b,
                                      b1c, W2c, b2c,
                                      scale_w, out);
}